// round 15
// baseline (speedup 1.0000x reference)
#include <cuda_runtime.h>
#include <cuda_fp16.h>
#include <cstdint>

#define B_  256
#define T_  256
#define E_  384
#define H_  6
#define D_  64
#define BT_ (B_ * T_)
#define NQKV_ 1152
#define NW_   1536
#define QSCALE (0.125f * 1.44269504088896f)   // 1/sqrt(D) * log2(e)

// ---------------- device scratch (all fp16 single) ----------------
__device__ __half g_xh[BT_*E_];
__device__ __half g_ah[BT_*E_];
__device__ __half g_wh[NW_*E_];
__device__ __half g_qh[B_*H_*T_*D_];
__device__ __half g_kh[B_*H_*T_*D_];
__device__ __half g_vh[B_*H_*T_*D_];            // V [b,h,t,d] like K

// ---------------- wrappers ----------------
__device__ __forceinline__ uint32_t smem_u32(const void* p) {
    uint32_t a;
    asm("{ .reg .u64 t; cvta.to.shared.u64 t, %1; cvt.u32.u64 %0, t; }" : "=r"(a) : "l"(p));
    return a;
}
__device__ __forceinline__ void ldsm_x4(uint32_t r[4], uint32_t addr) {
    asm volatile("ldmatrix.sync.aligned.m8n8.x4.shared.b16 {%0,%1,%2,%3}, [%4];"
                 : "=r"(r[0]), "=r"(r[1]), "=r"(r[2]), "=r"(r[3]) : "r"(addr));
}
__device__ __forceinline__ void ldsm_x4t(uint32_t r[4], uint32_t addr) {
    asm volatile("ldmatrix.sync.aligned.m8n8.x4.trans.shared.b16 {%0,%1,%2,%3}, [%4];"
                 : "=r"(r[0]), "=r"(r[1]), "=r"(r[2]), "=r"(r[3]) : "r"(addr));
}
__device__ __forceinline__ void ldsm_x2t(uint32_t r[2], uint32_t addr) {
    asm volatile("ldmatrix.sync.aligned.m8n8.x2.trans.shared.b16 {%0,%1}, [%2];"
                 : "=r"(r[0]), "=r"(r[1]) : "r"(addr));
}
__device__ __forceinline__ void mma16816h(float c[4], const uint32_t a[4],
                                          uint32_t b0, uint32_t b1) {
    asm volatile(
        "mma.sync.aligned.m16n8k16.row.col.f32.f16.f16.f32 "
        "{%0,%1,%2,%3}, {%4,%5,%6,%7}, {%8,%9}, {%0,%1,%2,%3};"
        : "+f"(c[0]), "+f"(c[1]), "+f"(c[2]), "+f"(c[3])
        : "r"(a[0]), "r"(a[1]), "r"(a[2]), "r"(a[3]), "r"(b0), "r"(b1));
}
__device__ __forceinline__ void cp16(uint32_t dst, const void* src) {
    asm volatile("cp.async.ca.shared.global [%0], [%1], 16;" :: "r"(dst), "l"(src));
}
#define CP_COMMIT() asm volatile("cp.async.commit_group;" ::: "memory")
#define CP_WAIT(n)  asm volatile("cp.async.wait_group %0;" :: "n"(n) : "memory")

__device__ __forceinline__ uint32_t packh(float a, float b) {
    __half2 h = __floats2half2_rn(a, b);
    return *reinterpret_cast<uint32_t*>(&h);
}
__device__ __forceinline__ uint32_t h2ex2(uint32_t x) {
    uint32_t r;
    asm("ex2.approx.f16x2 %0, %1;" : "=r"(r) : "r"(x));
    return r;
}

// ================= fused prep kernel =================
#define CONVX_BLOCKS ((BT_ * E_) / 4 / 256)     // 24576
#define CONVW_BLOCKS ((NW_ * E_) / 4 / 256)     // 576

__global__ void conv_kernel(const float* __restrict__ x,
                            const float* __restrict__ Wq, const float* __restrict__ Wk,
                            const float* __restrict__ Wv, const float* __restrict__ Wo) {
    int blk = blockIdx.x;
    if (blk < CONVX_BLOCKS) {
        size_t i = ((size_t)blk * 256 + threadIdx.x) * 4;
        float4 v = *reinterpret_cast<const float4*>(x + i);
        uint2 hv;
        hv.x = packh(v.x, v.y);
        hv.y = packh(v.z, v.w);
        *reinterpret_cast<uint2*>(g_xh + i) = hv;
    } else {
        int idx = (blk - CONVX_BLOCKS) * 256 + threadIdx.x;
        int n = idx / 96;
        int e0 = (idx % 96) * 4;
        float v[4];
        if (n < NQKV_) {
            int which = n / 384, r = n % 384, h = r >> 6, d = r & 63;
            const float* W = (which == 0) ? Wq : ((which == 1) ? Wk : Wv);
#pragma unroll
            for (int j = 0; j < 4; j++) v[j] = W[((size_t)h * E_ + e0 + j) * D_ + d];
        } else {
            int no = n - NQKV_;
#pragma unroll
            for (int j = 0; j < 4; j++) v[j] = Wo[(size_t)(e0 + j) * E_ + no];
        }
        uint2 hv;
        hv.x = packh(v[0], v[1]);
        hv.y = packh(v[2], v[3]);
        *reinterpret_cast<uint2*>(g_wh + (size_t)n * E_ + e0) = hv;
    }
}

// ====== single-product fp16 mma.sync GEMM (K=64 chunks, 2-stage, 1 sync) ===
#define APAD 72
#define GM_CH (128 * APAD)
#define GM_STAGE (2 * GM_CH)
#define GM_SMEM_BYTES (2 * GM_STAGE * 2)        // 73728 bytes

template <int MODE>
__global__ __launch_bounds__(256, 2) void gemm_kernel(float* __restrict__ outp,
                                                      const float* __restrict__ bo)
{
    extern __shared__ __half dsm[];

    const int tid = threadIdx.x;
    const int wid = tid >> 5, lane = tid & 31;
    const int wm = (wid & 3) * 32;
    const int wn = (wid >> 2) * 64;
    const int n0 = blockIdx.x * 128;
    const int m0 = blockIdx.y * 128;

    const __half* __restrict__ pA = (MODE == 0) ? g_xh : g_ah;
    const int nbase = (MODE == 0) ? n0 : (NQKV_ + n0);

    const uint32_t sb = smem_u32(dsm);

    float acc[2][8][4];
#pragma unroll
    for (int mt = 0; mt < 2; mt++)
#pragma unroll
        for (int nt = 0; nt < 8; nt++)
#pragma unroll
            for (int q = 0; q < 4; q++) acc[mt][nt][q] = 0.f;

    const int aRow = (lane & 15);
    const int aKseg = (lane >> 4) * 8;
    const int bRowOff = (lane & 7) + ((lane >> 4) << 3);
    const int bKoff = ((lane >> 3) & 1) * 8;

    auto prefetch = [&](int stage, int c) {
        uint32_t base = sb + (uint32_t)stage * GM_STAGE * 2;
#pragma unroll
        for (int i = 0; i < 4; i++) {
            int u = tid + 256 * i;
            int row = u >> 3, seg = u & 7;
            size_t ga = (size_t)(m0 + row) * E_ + c * 64 + seg * 8;
            size_t gb = (size_t)(nbase + row) * E_ + c * 64 + seg * 8;
            uint32_t so = (uint32_t)(row * APAD + seg * 8) * 2;
            cp16(base + so,             pA + ga);
            cp16(base + GM_CH * 2 + so, g_wh + gb);
        }
    };

    prefetch(0, 0);
    CP_COMMIT();

    for (int c = 0; c < 6; c++) {
        CP_WAIT(0);
        __syncthreads();
        if (c + 1 < 6) {
            prefetch((c + 1) & 1, c + 1);
            CP_COMMIT();
        }

        const uint32_t bA = sb + (uint32_t)(c & 1) * GM_STAGE * 2;
        const uint32_t bB = bA + GM_CH * 2;

#pragma unroll
        for (int ks = 0; ks < 4; ks++) {
            uint32_t ah[2][4];
#pragma unroll
            for (int mt = 0; mt < 2; mt++) {
                uint32_t off = (uint32_t)((wm + mt * 16 + aRow) * APAD + ks * 16 + aKseg) * 2;
                ldsm_x4(ah[mt], bA + off);
            }
#pragma unroll
            for (int ng = 0; ng < 4; ng++) {
                uint32_t bh[4];
                uint32_t boff = (uint32_t)((wn + ng * 16 + bRowOff) * APAD + ks * 16 + bKoff) * 2;
                ldsm_x4(bh, bB + boff);
#pragma unroll
                for (int mt = 0; mt < 2; mt++) {
                    mma16816h(acc[mt][ng * 2 + 0], ah[mt], bh[0], bh[1]);
                    mma16816h(acc[mt][ng * 2 + 1], ah[mt], bh[2], bh[3]);
                }
            }
        }
    }

    // ---------------- epilogue ----------------
    const int rOff = lane >> 2;
    const int cOff = (lane & 3) * 2;

    if (MODE == 0) {
        const int which = n0 / 384;
        const int r0 = (n0 % 384) + wn;
        const int hh = r0 >> 6;
        const float scale = (which == 0) ? QSCALE : 1.0f;
        __half* basep = (which == 0) ? g_qh : ((which == 1) ? g_kh : g_vh);
#pragma unroll
        for (int mt = 0; mt < 2; mt++) {
#pragma unroll
            for (int half = 0; half < 2; half++) {
                int m = m0 + wm + mt * 16 + rOff + half * 8;
                int bb = m >> 8, tt = m & 255;
                __half* dst = basep + ((size_t)(bb * H_ + hh) * T_ + tt) * D_;
#pragma unroll
                for (int nt = 0; nt < 8; nt++) {
                    *reinterpret_cast<uint32_t*>(dst + nt * 8 + cOff) =
                        packh(acc[mt][nt][half * 2 + 0] * scale,
                              acc[mt][nt][half * 2 + 1] * scale);
                }
            }
        }
    } else {
#pragma unroll
        for (int mt = 0; mt < 2; mt++) {
#pragma unroll
            for (int half = 0; half < 2; half++) {
                int m = m0 + wm + mt * 16 + rOff + half * 8;
                float* dst = outp + (size_t)m * E_ + n0 + wn;
#pragma unroll
                for (int nt = 0; nt < 8; nt++) {
                    int n = nt * 8 + cOff;
                    float2 bv = *reinterpret_cast<const float2*>(bo + n0 + wn + n);
                    float2 v;
                    v.x = acc[mt][nt][half * 2 + 0] + bv.x;
                    v.y = acc[mt][nt][half * 2 + 1] + bv.y;
                    *reinterpret_cast<float2*>(dst + n) = v;
                }
            }
        }
    }
}

// ==== flash attention: 128 q-rows/CTA, SHARED K/V ldsm across q-tiles,  ====
// ==== exp2-in-fp16 softmax, ones-COLUMN MMA row sums, one sync/tile     ====
#define AT_S 72
#define AT_BUF (2 * 64 * AT_S)                   // K(64xAT_S) + V(64xAT_S) halves

__global__ __launch_bounds__(128) void attn_kernel()
{
    __shared__ __half smb[2 * AT_BUF];

    const int tid = threadIdx.x;
    const int wid = tid >> 5, lane = tid & 31;
    const int qt2 = blockIdx.x, h = blockIdx.y, b = blockIdx.z;
    const int bh = b * H_ + h;
    const int qbase = qt2 * 128;

    const __half* qp = g_qh + (size_t)bh * T_ * D_;
    const __half* kp = g_kh + (size_t)bh * T_ * D_;
    const __half* vp = g_vh + (size_t)bh * T_ * D_;

    const uint32_t sbase = smem_u32(smb);
    const uint32_t vOff = 64 * AT_S;

    // ---- stage 128 Q rows + ones columns ----
#pragma unroll
    for (int i = 0; i < 8; i++) {
        int u = tid + 128 * i;
        int row = u >> 3, seg = u & 7;
        *reinterpret_cast<uint4*>(&smb[row * AT_S + seg * 8]) =
            *reinterpret_cast<const uint4*>(qp + (size_t)(qbase + row) * D_ + seg * 8);
    }
    for (int i = tid; i < 2 * 64 * 8; i += 128) {
        int s = i >> 9, r = (i >> 3) & 63, c = i & 7;
        smb[s * AT_BUF + vOff + r * AT_S + 64 + c] =
            (c == 0) ? __float2half(1.f) : __float2half(0.f);
    }
    __syncthreads();

    uint32_t aQA[4][4], aQB[4][4], eF[2];
    {
        const int aRow = lane & 15, aSeg = (lane >> 4) * 8;
#pragma unroll
        for (int ks = 0; ks < 4; ks++) {
            uint32_t offA = (uint32_t)((wid * 16 + aRow) * AT_S + ks * 16 + aSeg) * 2;
            ldsm_x4(aQA[ks], sbase + offA);
            uint32_t offB = (uint32_t)((64 + wid * 16 + aRow) * AT_S + ks * 16 + aSeg) * 2;
            ldsm_x4(aQB[ks], sbase + offB);
        }
        uint32_t eoff = (uint32_t)(vOff +
            ((lane & 7) + ((lane >> 3) & 1) * 8) * AT_S + 64) * 2;
        ldsm_x2t(eF, sbase + eoff);
    }
    __syncthreads();

    auto stage = [&](int s, int kt) {
        uint32_t base = sbase + (uint32_t)s * AT_BUF * 2;
#pragma unroll
        for (int i = 0; i < 4; i++) {
            int u = tid + 128 * i;
            int row = u >> 3, seg = u & 7;
            uint32_t so = (uint32_t)(row * AT_S + seg * 8) * 2;
            cp16(base + so,            kp + (size_t)(kt * 64 + row) * D_ + seg * 8);
            cp16(base + vOff * 2 + so, vp + (size_t)(kt * 64 + row) * D_ + seg * 8);
        }
    };

    float oaccA[8][4], oaccB[8][4], oaccEA[4], oaccEB[4];
#pragma unroll
    for (int nt = 0; nt < 8; nt++)
#pragma unroll
        for (int q = 0; q < 4; q++) { oaccA[nt][q] = 0.f; oaccB[nt][q] = 0.f; }
#pragma unroll
    for (int q = 0; q < 4; q++) { oaccEA[q] = 0.f; oaccEB[q] = 0.f; }

    const int bRowOff = (lane & 7) + ((lane >> 4) << 3);   // K: n-row
    const int bKoff = ((lane >> 3) & 1) * 8;               // K: k-col
    const int vRow = (lane & 7) + ((lane >> 3) & 1) * 8;   // V (trans): k-row
    const int vCol = ((lane >> 4) & 1) * 8;                // V: n-col
    const int ktmax = 2 * qt2 + 1;

    stage(0, 0);
    CP_COMMIT();

    for (int kt = 0; kt <= ktmax; kt++) {
        CP_WAIT(0);
        __syncthreads();
        if (kt < ktmax) {
            stage((kt + 1) & 1, kt + 1);
            CP_COMMIT();
        }

        const uint32_t bK = sbase + (uint32_t)(kt & 1) * AT_BUF * 2;
        const uint32_t bV = bK + vOff * 2;

        const bool actA = (kt <= 2 * qt2);       // tile A causally alive
        const bool maskA = (kt == 2 * qt2);
        const bool maskB = (kt == ktmax);

        // ---- S phase: one K ldsm feeds both q-tiles ----
        float saccA[8][4], saccB[8][4];
#pragma unroll
        for (int nt = 0; nt < 8; nt++)
#pragma unroll
            for (int q = 0; q < 4; q++) { saccA[nt][q] = 0.f; saccB[nt][q] = 0.f; }
#pragma unroll
        for (int ks = 0; ks < 4; ks++) {
#pragma unroll
            for (int ng = 0; ng < 4; ng++) {
                uint32_t boff = (uint32_t)((ng * 16 + bRowOff) * AT_S + ks * 16 + bKoff) * 2;
                uint32_t bh4[4];
                ldsm_x4(bh4, bK + boff);
                if (actA) {
                    mma16816h(saccA[ng * 2 + 0], aQA[ks], bh4[0], bh4[1]);
                    mma16816h(saccA[ng * 2 + 1], aQA[ks], bh4[2], bh4[3]);
                }
                mma16816h(saccB[ng * 2 + 0], aQB[ks], bh4[0], bh4[1]);
                mma16816h(saccB[ng * 2 + 1], aQB[ks], bh4[2], bh4[3]);
            }
        }

        // ---- causal masks (local row/col compare valid on diagonal tiles) ----
        if (maskA) {
#pragma unroll
            for (int nt = 0; nt < 8; nt++)
#pragma unroll
                for (int j = 0; j < 4; j++) {
                    int rloc = wid * 16 + (lane >> 2) + (j >> 1) * 8;
                    int cloc = nt * 8 + (lane & 3) * 2 + (j & 1);
                    if (cloc > rloc) saccA[nt][j] = -1e30f;
                }
        }
        if (maskB) {
#pragma unroll
            for (int nt = 0; nt < 8; nt++)
#pragma unroll
                for (int j = 0; j < 4; j++) {
                    int rloc = wid * 16 + (lane >> 2) + (j >> 1) * 8;
                    int cloc = nt * 8 + (lane & 3) * 2 + (j & 1);
                    if (cloc > rloc) saccB[nt][j] = -1e30f;
                }
        }

        // ---- softmax (exp2 in fp16) -> A-fragments ----
        uint32_t aPA[4][4], aPB[4][4];
#pragma unroll
        for (int ks = 0; ks < 4; ks++) {
            if (actA) {
                aPA[ks][0] = h2ex2(packh(saccA[2 * ks][0],     saccA[2 * ks][1]));
                aPA[ks][1] = h2ex2(packh(saccA[2 * ks][2],     saccA[2 * ks][3]));
                aPA[ks][2] = h2ex2(packh(saccA[2 * ks + 1][0], saccA[2 * ks + 1][1]));
                aPA[ks][3] = h2ex2(packh(saccA[2 * ks + 1][2], saccA[2 * ks + 1][3]));
            }
            aPB[ks][0] = h2ex2(packh(saccB[2 * ks][0],     saccB[2 * ks][1]));
            aPB[ks][1] = h2ex2(packh(saccB[2 * ks][2],     saccB[2 * ks][3]));
            aPB[ks][2] = h2ex2(packh(saccB[2 * ks + 1][0], saccB[2 * ks + 1][1]));
            aPB[ks][3] = h2ex2(packh(saccB[2 * ks + 1][2], saccB[2 * ks + 1][3]));
        }

        // ---- PV phase: one V ldsm feeds both q-tiles; ones-column sums ----
#pragma unroll
        for (int ks = 0; ks < 4; ks++) {
#pragma unroll
            for (int ng = 0; ng < 4; ng++) {
                uint32_t boff = (uint32_t)((ks * 16 + vRow) * AT_S + ng * 16 + vCol) * 2;
                uint32_t vh4[4];
                ldsm_x4t(vh4, bV + boff);
                if (actA) {
                    mma16816h(oaccA[ng * 2 + 0], aPA[ks], vh4[0], vh4[1]);
                    mma16816h(oaccA[ng * 2 + 1], aPA[ks], vh4[2], vh4[3]);
                }
                mma16816h(oaccB[ng * 2 + 0], aPB[ks], vh4[0], vh4[1]);
                mma16816h(oaccB[ng * 2 + 1], aPB[ks], vh4[2], vh4[3]);
            }
            if (actA) mma16816h(oaccEA, aPA[ks], eF[0], eF[1]);
            mma16816h(oaccEB, aPB[ks], eF[0], eF[1]);
        }
    }

    // normalize: row sum in ones-tile col 0 (lanes with lane%4==0)
#pragma unroll
    for (int tb = 0; tb < 2; tb++) {
        float (*oacc)[4] = tb ? oaccB : oaccA;
        float* oaccE = tb ? oaccEB : oaccEA;
#pragma unroll
        for (int hf = 0; hf < 2; hf++) {
            float l = __shfl_sync(0xffffffffu, oaccE[hf * 2], lane & 28);
            int q = qbase + tb * 64 + wid * 16 + (lane >> 2) + hf * 8;
            float inv = 1.0f / l;
            size_t basei = (size_t)(b * T_ + q) * E_ + h * 64 + (lane & 3) * 2;
#pragma unroll
            for (int nt = 0; nt < 8; nt++) {
                *reinterpret_cast<uint32_t*>(g_ah + basei + nt * 8) =
                    packh(oacc[nt][hf * 2 + 0] * inv, oacc[nt][hf * 2 + 1] * inv);
            }
        }
    }
}

// ================= launcher =================
extern "C" void kernel_launch(void* const* d_in, const int* in_sizes, int n_in,
                              void* d_out, int out_size) {
    const float* x  = (const float*)d_in[0];
    const float* Wq = (const float*)d_in[1];
    const float* Wk = (const float*)d_in[2];
    const float* Wv = (const float*)d_in[3];
    const float* Wo = (const float*)d_in[4];
    const float* bo = (const float*)d_in[5];
    float* out = (float*)d_out;

    cudaFuncSetAttribute(gemm_kernel<0>, cudaFuncAttributeMaxDynamicSharedMemorySize, GM_SMEM_BYTES);
    cudaFuncSetAttribute(gemm_kernel<1>, cudaFuncAttributeMaxDynamicSharedMemorySize, GM_SMEM_BYTES);

    conv_kernel<<<CONVX_BLOCKS + CONVW_BLOCKS, 256>>>(x, Wq, Wk, Wv, Wo);

    dim3 g1(NQKV_ / 128, BT_ / 128);
    gemm_kernel<0><<<g1, 256, GM_SMEM_BYTES>>>(nullptr, nullptr);

    dim3 g2(T_ / 128, H_, B_);
    attn_kernel<<<g2, 128>>>();

    dim3 g3(E_ / 128, BT_ / 128);
    gemm_kernel<1><<<g3, 256, GM_SMEM_BYTES>>>(out, bo);
}

// round 16
// speedup vs baseline: 1.0199x; 1.0199x over previous
#include <cuda_runtime.h>
#include <cuda_fp16.h>
#include <cstdint>

#define B_  256
#define T_  256
#define E_  384
#define H_  6
#define D_  64
#define BT_ (B_ * T_)
#define NQKV_ 1152
#define NW_   1536
#define QSCALE (0.125f * 1.44269504088896f)   // 1/sqrt(D) * log2(e)

// ---------------- device scratch (all fp16 single) ----------------
__device__ __half g_xh[BT_*E_];
__device__ __half g_ah[BT_*E_];
__device__ __half g_wh[NW_*E_];
__device__ __half g_qh[B_*H_*T_*D_];
__device__ __half g_kh[B_*H_*T_*D_];
__device__ __half g_vh[B_*H_*T_*D_];            // V [b,h,t,d] like K

// ---------------- wrappers ----------------
__device__ __forceinline__ uint32_t smem_u32(const void* p) {
    uint32_t a;
    asm("{ .reg .u64 t; cvta.to.shared.u64 t, %1; cvt.u32.u64 %0, t; }" : "=r"(a) : "l"(p));
    return a;
}
__device__ __forceinline__ void ldsm_x4(uint32_t r[4], uint32_t addr) {
    asm volatile("ldmatrix.sync.aligned.m8n8.x4.shared.b16 {%0,%1,%2,%3}, [%4];"
                 : "=r"(r[0]), "=r"(r[1]), "=r"(r[2]), "=r"(r[3]) : "r"(addr));
}
__device__ __forceinline__ void ldsm_x4t(uint32_t r[4], uint32_t addr) {
    asm volatile("ldmatrix.sync.aligned.m8n8.x4.trans.shared.b16 {%0,%1,%2,%3}, [%4];"
                 : "=r"(r[0]), "=r"(r[1]), "=r"(r[2]), "=r"(r[3]) : "r"(addr));
}
__device__ __forceinline__ void ldsm_x2t(uint32_t r[2], uint32_t addr) {
    asm volatile("ldmatrix.sync.aligned.m8n8.x2.trans.shared.b16 {%0,%1}, [%2];"
                 : "=r"(r[0]), "=r"(r[1]) : "r"(addr));
}
__device__ __forceinline__ void mma16816h(float c[4], const uint32_t a[4],
                                          uint32_t b0, uint32_t b1) {
    asm volatile(
        "mma.sync.aligned.m16n8k16.row.col.f32.f16.f16.f32 "
        "{%0,%1,%2,%3}, {%4,%5,%6,%7}, {%8,%9}, {%0,%1,%2,%3};"
        : "+f"(c[0]), "+f"(c[1]), "+f"(c[2]), "+f"(c[3])
        : "r"(a[0]), "r"(a[1]), "r"(a[2]), "r"(a[3]), "r"(b0), "r"(b1));
}
__device__ __forceinline__ void cp16(uint32_t dst, const void* src) {
    asm volatile("cp.async.ca.shared.global [%0], [%1], 16;" :: "r"(dst), "l"(src));
}
#define CP_COMMIT() asm volatile("cp.async.commit_group;" ::: "memory")
#define CP_WAIT(n)  asm volatile("cp.async.wait_group %0;" :: "n"(n) : "memory")

__device__ __forceinline__ uint32_t packh(float a, float b) {
    __half2 h = __floats2half2_rn(a, b);
    return *reinterpret_cast<uint32_t*>(&h);
}
__device__ __forceinline__ uint32_t h2ex2(uint32_t x) {
    uint32_t r;
    asm("ex2.approx.f16x2 %0, %1;" : "=r"(r) : "r"(x));
    return r;
}

// ================= fused prep kernel =================
#define CONVX_BLOCKS ((BT_ * E_) / 4 / 256)     // 24576
#define CONVW_BLOCKS ((NW_ * E_) / 4 / 256)     // 576

__global__ void conv_kernel(const float* __restrict__ x,
                            const float* __restrict__ Wq, const float* __restrict__ Wk,
                            const float* __restrict__ Wv, const float* __restrict__ Wo) {
    int blk = blockIdx.x;
    if (blk < CONVX_BLOCKS) {
        size_t i = ((size_t)blk * 256 + threadIdx.x) * 4;
        float4 v = *reinterpret_cast<const float4*>(x + i);
        uint2 hv;
        hv.x = packh(v.x, v.y);
        hv.y = packh(v.z, v.w);
        *reinterpret_cast<uint2*>(g_xh + i) = hv;
    } else {
        int idx = (blk - CONVX_BLOCKS) * 256 + threadIdx.x;
        int n = idx / 96;
        int e0 = (idx % 96) * 4;
        float v[4];
        if (n < NQKV_) {
            int which = n / 384, r = n % 384, h = r >> 6, d = r & 63;
            const float* W = (which == 0) ? Wq : ((which == 1) ? Wk : Wv);
#pragma unroll
            for (int j = 0; j < 4; j++) v[j] = W[((size_t)h * E_ + e0 + j) * D_ + d];
        } else {
            int no = n - NQKV_;
#pragma unroll
            for (int j = 0; j < 4; j++) v[j] = Wo[(size_t)(e0 + j) * E_ + no];
        }
        uint2 hv;
        hv.x = packh(v[0], v[1]);
        hv.y = packh(v[2], v[3]);
        *reinterpret_cast<uint2*>(g_wh + (size_t)n * E_ + e0) = hv;
    }
}

// ====== single-product fp16 mma.sync GEMM (K=64 chunks, 2-stage, 1 sync) ===
#define APAD 72
#define GM_CH (128 * APAD)
#define GM_STAGE (2 * GM_CH)
#define GM_SMEM_BYTES (2 * GM_STAGE * 2)        // 73728 bytes

template <int MODE>
__global__ __launch_bounds__(256, 2) void gemm_kernel(float* __restrict__ outp,
                                                      const float* __restrict__ bo)
{
    extern __shared__ __half dsm[];

    const int tid = threadIdx.x;
    const int wid = tid >> 5, lane = tid & 31;
    const int wm = (wid & 3) * 32;
    const int wn = (wid >> 2) * 64;
    const int n0 = blockIdx.x * 128;
    const int m0 = blockIdx.y * 128;

    const __half* __restrict__ pA = (MODE == 0) ? g_xh : g_ah;
    const int nbase = (MODE == 0) ? n0 : (NQKV_ + n0);

    const uint32_t sb = smem_u32(dsm);

    float acc[2][8][4];
#pragma unroll
    for (int mt = 0; mt < 2; mt++)
#pragma unroll
        for (int nt = 0; nt < 8; nt++)
#pragma unroll
            for (int q = 0; q < 4; q++) acc[mt][nt][q] = 0.f;

    const int aRow = (lane & 15);
    const int aKseg = (lane >> 4) * 8;
    const int bRowOff = (lane & 7) + ((lane >> 4) << 3);
    const int bKoff = ((lane >> 3) & 1) * 8;

    auto prefetch = [&](int stage, int c) {
        uint32_t base = sb + (uint32_t)stage * GM_STAGE * 2;
#pragma unroll
        for (int i = 0; i < 4; i++) {
            int u = tid + 256 * i;
            int row = u >> 3, seg = u & 7;
            size_t ga = (size_t)(m0 + row) * E_ + c * 64 + seg * 8;
            size_t gb = (size_t)(nbase + row) * E_ + c * 64 + seg * 8;
            uint32_t so = (uint32_t)(row * APAD + seg * 8) * 2;
            cp16(base + so,             pA + ga);
            cp16(base + GM_CH * 2 + so, g_wh + gb);
        }
    };

    prefetch(0, 0);
    CP_COMMIT();

    for (int c = 0; c < 6; c++) {
        CP_WAIT(0);
        __syncthreads();
        if (c + 1 < 6) {
            prefetch((c + 1) & 1, c + 1);
            CP_COMMIT();
        }

        const uint32_t bA = sb + (uint32_t)(c & 1) * GM_STAGE * 2;
        const uint32_t bB = bA + GM_CH * 2;

#pragma unroll
        for (int ks = 0; ks < 4; ks++) {
            uint32_t ah[2][4];
#pragma unroll
            for (int mt = 0; mt < 2; mt++) {
                uint32_t off = (uint32_t)((wm + mt * 16 + aRow) * APAD + ks * 16 + aKseg) * 2;
                ldsm_x4(ah[mt], bA + off);
            }
#pragma unroll
            for (int ng = 0; ng < 4; ng++) {
                uint32_t bh[4];
                uint32_t boff = (uint32_t)((wn + ng * 16 + bRowOff) * APAD + ks * 16 + bKoff) * 2;
                ldsm_x4(bh, bB + boff);
#pragma unroll
                for (int mt = 0; mt < 2; mt++) {
                    mma16816h(acc[mt][ng * 2 + 0], ah[mt], bh[0], bh[1]);
                    mma16816h(acc[mt][ng * 2 + 1], ah[mt], bh[2], bh[3]);
                }
            }
        }
    }

    // ---------------- epilogue ----------------
    const int rOff = lane >> 2;
    const int cOff = (lane & 3) * 2;

    if (MODE == 0) {
        const int which = n0 / 384;
        const int r0 = (n0 % 384) + wn;
        const int hh = r0 >> 6;
        const float scale = (which == 0) ? QSCALE : 1.0f;
        __half* basep = (which == 0) ? g_qh : ((which == 1) ? g_kh : g_vh);
#pragma unroll
        for (int mt = 0; mt < 2; mt++) {
#pragma unroll
            for (int half = 0; half < 2; half++) {
                int m = m0 + wm + mt * 16 + rOff + half * 8;
                int bb = m >> 8, tt = m & 255;
                __half* dst = basep + ((size_t)(bb * H_ + hh) * T_ + tt) * D_;
#pragma unroll
                for (int nt = 0; nt < 8; nt++) {
                    *reinterpret_cast<uint32_t*>(dst + nt * 8 + cOff) =
                        packh(acc[mt][nt][half * 2 + 0] * scale,
                              acc[mt][nt][half * 2 + 1] * scale);
                }
            }
        }
    } else {
#pragma unroll
        for (int mt = 0; mt < 2; mt++) {
#pragma unroll
            for (int half = 0; half < 2; half++) {
                int m = m0 + wm + mt * 16 + rOff + half * 8;
                float* dst = outp + (size_t)m * E_ + n0 + wn;
#pragma unroll
                for (int nt = 0; nt < 8; nt++) {
                    int n = nt * 8 + cOff;
                    float2 bv = *reinterpret_cast<const float2*>(bo + n0 + wn + n);
                    float2 v;
                    v.x = acc[mt][nt][half * 2 + 0] + bv.x;
                    v.y = acc[mt][nt][half * 2 + 1] + bv.y;
                    *reinterpret_cast<float2*>(dst + n) = v;
                }
            }
        }
    }
}

// ==== flash attention: 128 q-rows/CTA, sequential S-phases (reg-frugal), ====
// ==== SHARED V ldsm in PV phase, exp2-in-fp16 softmax, ones-column sums  ====
#define AT_S 72
#define AT_BUF (2 * 64 * AT_S)                   // K(64xAT_S) + V(64xAT_S) halves

__global__ __launch_bounds__(128, 3) void attn_kernel()
{
    __shared__ __half smb[2 * AT_BUF];

    const int tid = threadIdx.x;
    const int wid = tid >> 5, lane = tid & 31;
    const int qt2 = blockIdx.x, h = blockIdx.y, b = blockIdx.z;
    const int bh = b * H_ + h;
    const int qbase = qt2 * 128;

    const __half* qp = g_qh + (size_t)bh * T_ * D_;
    const __half* kp = g_kh + (size_t)bh * T_ * D_;
    const __half* vp = g_vh + (size_t)bh * T_ * D_;

    const uint32_t sbase = smem_u32(smb);
    const uint32_t vOff = 64 * AT_S;

    // ---- stage 128 Q rows + ones columns ----
#pragma unroll
    for (int i = 0; i < 8; i++) {
        int u = tid + 128 * i;
        int row = u >> 3, seg = u & 7;
        *reinterpret_cast<uint4*>(&smb[row * AT_S + seg * 8]) =
            *reinterpret_cast<const uint4*>(qp + (size_t)(qbase + row) * D_ + seg * 8);
    }
    for (int i = tid; i < 2 * 64 * 8; i += 128) {
        int s = i >> 9, r = (i >> 3) & 63, c = i & 7;
        smb[s * AT_BUF + vOff + r * AT_S + 64 + c] =
            (c == 0) ? __float2half(1.f) : __float2half(0.f);
    }
    __syncthreads();

    uint32_t aQA[4][4], aQB[4][4], eF[2];
    {
        const int aRow = lane & 15, aSeg = (lane >> 4) * 8;
#pragma unroll
        for (int ks = 0; ks < 4; ks++) {
            uint32_t offA = (uint32_t)((wid * 16 + aRow) * AT_S + ks * 16 + aSeg) * 2;
            ldsm_x4(aQA[ks], sbase + offA);
            uint32_t offB = (uint32_t)((64 + wid * 16 + aRow) * AT_S + ks * 16 + aSeg) * 2;
            ldsm_x4(aQB[ks], sbase + offB);
        }
        uint32_t eoff = (uint32_t)(vOff +
            ((lane & 7) + ((lane >> 3) & 1) * 8) * AT_S + 64) * 2;
        ldsm_x2t(eF, sbase + eoff);
    }
    __syncthreads();

    auto stage = [&](int s, int kt) {
        uint32_t base = sbase + (uint32_t)s * AT_BUF * 2;
#pragma unroll
        for (int i = 0; i < 4; i++) {
            int u = tid + 128 * i;
            int row = u >> 3, seg = u & 7;
            uint32_t so = (uint32_t)(row * AT_S + seg * 8) * 2;
            cp16(base + so,            kp + (size_t)(kt * 64 + row) * D_ + seg * 8);
            cp16(base + vOff * 2 + so, vp + (size_t)(kt * 64 + row) * D_ + seg * 8);
        }
    };

    float oaccA[8][4], oaccB[8][4], oaccEA[4], oaccEB[4];
#pragma unroll
    for (int nt = 0; nt < 8; nt++)
#pragma unroll
        for (int q = 0; q < 4; q++) { oaccA[nt][q] = 0.f; oaccB[nt][q] = 0.f; }
#pragma unroll
    for (int q = 0; q < 4; q++) { oaccEA[q] = 0.f; oaccEB[q] = 0.f; }

    const int bRowOff = (lane & 7) + ((lane >> 4) << 3);   // K: n-row
    const int bKoff = ((lane >> 3) & 1) * 8;               // K: k-col
    const int vRow = (lane & 7) + ((lane >> 3) & 1) * 8;   // V (trans): k-row
    const int vCol = ((lane >> 4) & 1) * 8;                // V: n-col
    const int ktmax = 2 * qt2 + 1;

    stage(0, 0);
    CP_COMMIT();

    for (int kt = 0; kt <= ktmax; kt++) {
        CP_WAIT(0);
        __syncthreads();
        if (kt < ktmax) {
            stage((kt + 1) & 1, kt + 1);
            CP_COMMIT();
        }

        const uint32_t bK = sbase + (uint32_t)(kt & 1) * AT_BUF * 2;
        const uint32_t bV = bK + vOff * 2;
        const bool actA = (kt <= 2 * qt2);

        // ---- S phases, sequential (sacc reused): produce aP2[tb] fragments ----
        uint32_t aP2[2][4][4];
#pragma unroll
        for (int tb = 0; tb < 2; tb++) {
            if (tb == 0 && !actA) continue;
            uint32_t (*aQ)[4] = tb ? aQB : aQA;

            float sacc[8][4];
#pragma unroll
            for (int nt = 0; nt < 8; nt++)
#pragma unroll
                for (int q = 0; q < 4; q++) sacc[nt][q] = 0.f;
#pragma unroll
            for (int ks = 0; ks < 4; ks++) {
#pragma unroll
                for (int ng = 0; ng < 4; ng++) {
                    uint32_t boff = (uint32_t)((ng * 16 + bRowOff) * AT_S + ks * 16 + bKoff) * 2;
                    uint32_t bh4[4];
                    ldsm_x4(bh4, bK + boff);
                    mma16816h(sacc[ng * 2 + 0], aQ[ks], bh4[0], bh4[1]);
                    mma16816h(sacc[ng * 2 + 1], aQ[ks], bh4[2], bh4[3]);
                }
            }

            if (kt == 2 * qt2 + tb) {            // diagonal: causal mask
#pragma unroll
                for (int nt = 0; nt < 8; nt++)
#pragma unroll
                    for (int j = 0; j < 4; j++) {
                        int rloc = wid * 16 + (lane >> 2) + (j >> 1) * 8;
                        int cloc = nt * 8 + (lane & 3) * 2 + (j & 1);
                        if (cloc > rloc) sacc[nt][j] = -1e30f;
                    }
            }

#pragma unroll
            for (int ks = 0; ks < 4; ks++) {
                aP2[tb][ks][0] = h2ex2(packh(sacc[2 * ks][0],     sacc[2 * ks][1]));
                aP2[tb][ks][1] = h2ex2(packh(sacc[2 * ks][2],     sacc[2 * ks][3]));
                aP2[tb][ks][2] = h2ex2(packh(sacc[2 * ks + 1][0], sacc[2 * ks + 1][1]));
                aP2[tb][ks][3] = h2ex2(packh(sacc[2 * ks + 1][2], sacc[2 * ks + 1][3]));
            }
        }

        // ---- PV phase: ONE V ldsm feeds both q-tiles; ones-column row sums ----
#pragma unroll
        for (int ks = 0; ks < 4; ks++) {
#pragma unroll
            for (int ng = 0; ng < 4; ng++) {
                uint32_t boff = (uint32_t)((ks * 16 + vRow) * AT_S + ng * 16 + vCol) * 2;
                uint32_t vh4[4];
                ldsm_x4t(vh4, bV + boff);
                if (actA) {
                    mma16816h(oaccA[ng * 2 + 0], aP2[0][ks], vh4[0], vh4[1]);
                    mma16816h(oaccA[ng * 2 + 1], aP2[0][ks], vh4[2], vh4[3]);
                }
                mma16816h(oaccB[ng * 2 + 0], aP2[1][ks], vh4[0], vh4[1]);
                mma16816h(oaccB[ng * 2 + 1], aP2[1][ks], vh4[2], vh4[3]);
            }
            if (actA) mma16816h(oaccEA, aP2[0][ks], eF[0], eF[1]);
            mma16816h(oaccEB, aP2[1][ks], eF[0], eF[1]);
        }
    }

    // normalize: row sum in ones-tile col 0 (lanes with lane%4==0)
#pragma unroll
    for (int tb = 0; tb < 2; tb++) {
        float (*oacc)[4] = tb ? oaccB : oaccA;
        float* oaccE = tb ? oaccEB : oaccEA;
#pragma unroll
        for (int hf = 0; hf < 2; hf++) {
            float l = __shfl_sync(0xffffffffu, oaccE[hf * 2], lane & 28);
            int q = qbase + tb * 64 + wid * 16 + (lane >> 2) + hf * 8;
            float inv = 1.0f / l;
            size_t basei = (size_t)(b * T_ + q) * E_ + h * 64 + (lane & 3) * 2;
#pragma unroll
            for (int nt = 0; nt < 8; nt++) {
                *reinterpret_cast<uint32_t*>(g_ah + basei + nt * 8) =
                    packh(oacc[nt][hf * 2 + 0] * inv, oacc[nt][hf * 2 + 1] * inv);
            }
        }
    }
}

// ================= launcher =================
extern "C" void kernel_launch(void* const* d_in, const int* in_sizes, int n_in,
                              void* d_out, int out_size) {
    const float* x  = (const float*)d_in[0];
    const float* Wq = (const float*)d_in[1];
    const float* Wk = (const float*)d_in[2];
    const float* Wv = (const float*)d_in[3];
    const float* Wo = (const float*)d_in[4];
    const float* bo = (const float*)d_in[5];
    float* out = (float*)d_out;

    cudaFuncSetAttribute(gemm_kernel<0>, cudaFuncAttributeMaxDynamicSharedMemorySize, GM_SMEM_BYTES);
    cudaFuncSetAttribute(gemm_kernel<1>, cudaFuncAttributeMaxDynamicSharedMemorySize, GM_SMEM_BYTES);

    conv_kernel<<<CONVX_BLOCKS + CONVW_BLOCKS, 256>>>(x, Wq, Wk, Wv, Wo);

    dim3 g1(NQKV_ / 128, BT_ / 128);
    gemm_kernel<0><<<g1, 256, GM_SMEM_BYTES>>>(nullptr, nullptr);

    dim3 g2(T_ / 128, H_, B_);
    attn_kernel<<<g2, 128>>>();

    dim3 g3(E_ / 128, BT_ / 128);
    gemm_kernel<1><<<g3, 256, GM_SMEM_BYTES>>>(out, bo);
}

// round 17
// speedup vs baseline: 1.0501x; 1.0296x over previous
#include <cuda_runtime.h>
#include <cuda_fp16.h>
#include <cstdint>

#define B_  256
#define T_  256
#define E_  384
#define H_  6
#define D_  64
#define BT_ (B_ * T_)
#define NQKV_ 1152
#define NW_   1536
#define QSCALE (0.125f * 1.44269504088896f)   // 1/sqrt(D) * log2(e)

// ---------------- device scratch (all fp16 single) ----------------
__device__ __half g_xh[BT_*E_];
__device__ __half g_ah[BT_*E_];
__device__ __half g_wh[NW_*E_];
__device__ __half g_qh[B_*H_*T_*D_];
__device__ __half g_kh[B_*H_*T_*D_];
__device__ __half g_vh[B_*H_*T_*D_];            // V [b,h,t,d] like K

// ---------------- wrappers ----------------
__device__ __forceinline__ uint32_t smem_u32(const void* p) {
    uint32_t a;
    asm("{ .reg .u64 t; cvta.to.shared.u64 t, %1; cvt.u32.u64 %0, t; }" : "=r"(a) : "l"(p));
    return a;
}
__device__ __forceinline__ void ldsm_x4(uint32_t r[4], uint32_t addr) {
    asm volatile("ldmatrix.sync.aligned.m8n8.x4.shared.b16 {%0,%1,%2,%3}, [%4];"
                 : "=r"(r[0]), "=r"(r[1]), "=r"(r[2]), "=r"(r[3]) : "r"(addr));
}
__device__ __forceinline__ void ldsm_x4t(uint32_t r[4], uint32_t addr) {
    asm volatile("ldmatrix.sync.aligned.m8n8.x4.trans.shared.b16 {%0,%1,%2,%3}, [%4];"
                 : "=r"(r[0]), "=r"(r[1]), "=r"(r[2]), "=r"(r[3]) : "r"(addr));
}
__device__ __forceinline__ void ldsm_x2t(uint32_t r[2], uint32_t addr) {
    asm volatile("ldmatrix.sync.aligned.m8n8.x2.trans.shared.b16 {%0,%1}, [%2];"
                 : "=r"(r[0]), "=r"(r[1]) : "r"(addr));
}
__device__ __forceinline__ void mma16816h(float c[4], const uint32_t a[4],
                                          uint32_t b0, uint32_t b1) {
    asm volatile(
        "mma.sync.aligned.m16n8k16.row.col.f32.f16.f16.f32 "
        "{%0,%1,%2,%3}, {%4,%5,%6,%7}, {%8,%9}, {%0,%1,%2,%3};"
        : "+f"(c[0]), "+f"(c[1]), "+f"(c[2]), "+f"(c[3])
        : "r"(a[0]), "r"(a[1]), "r"(a[2]), "r"(a[3]), "r"(b0), "r"(b1));
}
__device__ __forceinline__ void cp16(uint32_t dst, const void* src) {
    asm volatile("cp.async.ca.shared.global [%0], [%1], 16;" :: "r"(dst), "l"(src));
}
#define CP_COMMIT() asm volatile("cp.async.commit_group;" ::: "memory")
#define CP_WAIT(n)  asm volatile("cp.async.wait_group %0;" :: "n"(n) : "memory")

__device__ __forceinline__ uint32_t packh(float a, float b) {
    __half2 h = __floats2half2_rn(a, b);
    return *reinterpret_cast<uint32_t*>(&h);
}
__device__ __forceinline__ uint32_t h2ex2(uint32_t x) {
    uint32_t r;
    asm("ex2.approx.f16x2 %0, %1;" : "=r"(r) : "r"(x));
    return r;
}

// ================= fused prep kernel (8 floats/thread) =================
#define CONVX_BLOCKS ((BT_ * E_) / 8 / 256)     // 12288
#define CONVW_BLOCKS ((NW_ * E_) / 4 / 256)     // 576

__global__ void conv_kernel(const float* __restrict__ x,
                            const float* __restrict__ Wq, const float* __restrict__ Wk,
                            const float* __restrict__ Wv, const float* __restrict__ Wo) {
    int blk = blockIdx.x;
    if (blk < CONVX_BLOCKS) {
        size_t i = ((size_t)blk * 256 + threadIdx.x) * 8;
        float4 v0 = *reinterpret_cast<const float4*>(x + i);
        float4 v1 = *reinterpret_cast<const float4*>(x + i + 4);
        uint4 hv;
        hv.x = packh(v0.x, v0.y);
        hv.y = packh(v0.z, v0.w);
        hv.z = packh(v1.x, v1.y);
        hv.w = packh(v1.z, v1.w);
        *reinterpret_cast<uint4*>(g_xh + i) = hv;
    } else {
        int idx = (blk - CONVX_BLOCKS) * 256 + threadIdx.x;
        int n = idx / 96;
        int e0 = (idx % 96) * 4;
        float v[4];
        if (n < NQKV_) {
            int which = n / 384, r = n % 384, h = r >> 6, d = r & 63;
            const float* W = (which == 0) ? Wq : ((which == 1) ? Wk : Wv);
#pragma unroll
            for (int j = 0; j < 4; j++) v[j] = W[((size_t)h * E_ + e0 + j) * D_ + d];
        } else {
            int no = n - NQKV_;
#pragma unroll
            for (int j = 0; j < 4; j++) v[j] = Wo[(size_t)(e0 + j) * E_ + no];
        }
        uint2 hv;
        hv.x = packh(v[0], v[1]);
        hv.y = packh(v[2], v[3]);
        *reinterpret_cast<uint2*>(g_wh + (size_t)n * E_ + e0) = hv;
    }
}

// ====== single-product fp16 mma.sync GEMM (K=64 chunks, 2-stage, 1 sync) ===
#define APAD 72
#define GM_CH (128 * APAD)
#define GM_STAGE (2 * GM_CH)
#define GM_SMEM_BYTES (2 * GM_STAGE * 2)        // 73728 bytes

template <int MODE>
__global__ __launch_bounds__(256, 2) void gemm_kernel(float* __restrict__ outp,
                                                      const float* __restrict__ bo)
{
    extern __shared__ __half dsm[];

    const int tid = threadIdx.x;
    const int wid = tid >> 5, lane = tid & 31;
    const int wm = (wid & 3) * 32;
    const int wn = (wid >> 2) * 64;
    const int n0 = blockIdx.x * 128;
    const int m0 = blockIdx.y * 128;

    const __half* __restrict__ pA = (MODE == 0) ? g_xh : g_ah;
    const int nbase = (MODE == 0) ? n0 : (NQKV_ + n0);

    const uint32_t sb = smem_u32(dsm);

    float acc[2][8][4];
#pragma unroll
    for (int mt = 0; mt < 2; mt++)
#pragma unroll
        for (int nt = 0; nt < 8; nt++)
#pragma unroll
            for (int q = 0; q < 4; q++) acc[mt][nt][q] = 0.f;

    const int aRow = (lane & 15);
    const int aKseg = (lane >> 4) * 8;
    const int bRowOff = (lane & 7) + ((lane >> 4) << 3);
    const int bKoff = ((lane >> 3) & 1) * 8;

    auto prefetch = [&](int stage, int c) {
        uint32_t base = sb + (uint32_t)stage * GM_STAGE * 2;
#pragma unroll
        for (int i = 0; i < 4; i++) {
            int u = tid + 256 * i;
            int row = u >> 3, seg = u & 7;
            size_t ga = (size_t)(m0 + row) * E_ + c * 64 + seg * 8;
            size_t gb = (size_t)(nbase + row) * E_ + c * 64 + seg * 8;
            uint32_t so = (uint32_t)(row * APAD + seg * 8) * 2;
            cp16(base + so,             pA + ga);
            cp16(base + GM_CH * 2 + so, g_wh + gb);
        }
    };

    prefetch(0, 0);
    CP_COMMIT();

    for (int c = 0; c < 6; c++) {
        CP_WAIT(0);
        __syncthreads();
        if (c + 1 < 6) {
            prefetch((c + 1) & 1, c + 1);
            CP_COMMIT();
        }

        const uint32_t bA = sb + (uint32_t)(c & 1) * GM_STAGE * 2;
        const uint32_t bB = bA + GM_CH * 2;

#pragma unroll
        for (int ks = 0; ks < 4; ks++) {
            uint32_t ah[2][4];
#pragma unroll
            for (int mt = 0; mt < 2; mt++) {
                uint32_t off = (uint32_t)((wm + mt * 16 + aRow) * APAD + ks * 16 + aKseg) * 2;
                ldsm_x4(ah[mt], bA + off);
            }
#pragma unroll
            for (int ng = 0; ng < 4; ng++) {
                uint32_t bh[4];
                uint32_t boff = (uint32_t)((wn + ng * 16 + bRowOff) * APAD + ks * 16 + bKoff) * 2;
                ldsm_x4(bh, bB + boff);
#pragma unroll
                for (int mt = 0; mt < 2; mt++) {
                    mma16816h(acc[mt][ng * 2 + 0], ah[mt], bh[0], bh[1]);
                    mma16816h(acc[mt][ng * 2 + 1], ah[mt], bh[2], bh[3]);
                }
            }
        }
    }

    // ---------------- epilogue ----------------
    const int rOff = lane >> 2;
    const int cOff = (lane & 3) * 2;

    if (MODE == 0) {
        const int which = n0 / 384;
        const int r0 = (n0 % 384) + wn;
        const int hh = r0 >> 6;
        const float scale = (which == 0) ? QSCALE : 1.0f;
        __half* basep = (which == 0) ? g_qh : ((which == 1) ? g_kh : g_vh);
#pragma unroll
        for (int mt = 0; mt < 2; mt++) {
#pragma unroll
            for (int half = 0; half < 2; half++) {
                int m = m0 + wm + mt * 16 + rOff + half * 8;
                int bb = m >> 8, tt = m & 255;
                __half* dst = basep + ((size_t)(bb * H_ + hh) * T_ + tt) * D_;
#pragma unroll
                for (int nt = 0; nt < 8; nt++) {
                    *reinterpret_cast<uint32_t*>(dst + nt * 8 + cOff) =
                        packh(acc[mt][nt][half * 2 + 0] * scale,
                              acc[mt][nt][half * 2 + 1] * scale);
                }
            }
        }
    } else {
#pragma unroll
        for (int mt = 0; mt < 2; mt++) {
#pragma unroll
            for (int half = 0; half < 2; half++) {
                int m = m0 + wm + mt * 16 + rOff + half * 8;
                float* dst = outp + (size_t)m * E_ + n0 + wn;
#pragma unroll
                for (int nt = 0; nt < 8; nt++) {
                    int n = nt * 8 + cOff;
                    float2 bv = *reinterpret_cast<const float2*>(bo + n0 + wn + n);
                    float2 v;
                    v.x = acc[mt][nt][half * 2 + 0] + bv.x;
                    v.y = acc[mt][nt][half * 2 + 1] + bv.y;
                    *reinterpret_cast<float2*>(dst + n) = v;
                }
            }
        }
    }
}

// ==== flash attention (R14 structure): 128 q-rows/CTA, per-tile sequential ====
// ==== processing, exp2-in-fp16 softmax, ones-COLUMN MMA row sums,          ====
// ==== cp.async double-buffered K/V with EARLY kt=0 prefetch (buf parity+1) ====
#define AT_S 72
#define AT_BUF (2 * 64 * AT_S)                   // K(64xAT_S) + V(64xAT_S) halves

__global__ __launch_bounds__(128, 3) void attn_kernel()
{
    __shared__ __half smb[2 * AT_BUF];

    const int tid = threadIdx.x;
    const int wid = tid >> 5, lane = tid & 31;
    const int qt2 = blockIdx.x, h = blockIdx.y, b = blockIdx.z;
    const int bh = b * H_ + h;
    const int qbase = qt2 * 128;

    const __half* qp = g_qh + (size_t)bh * T_ * D_;
    const __half* kp = g_kh + (size_t)bh * T_ * D_;
    const __half* vp = g_vh + (size_t)bh * T_ * D_;

    const uint32_t sbase = smem_u32(smb);
    const uint32_t vOff = 64 * AT_S;

    auto stage = [&](int s, int kt) {
        uint32_t base = sbase + (uint32_t)s * AT_BUF * 2;
#pragma unroll
        for (int i = 0; i < 4; i++) {
            int u = tid + 128 * i;
            int row = u >> 3, seg = u & 7;
            uint32_t so = (uint32_t)(row * AT_S + seg * 8) * 2;
            cp16(base + so,            kp + (size_t)(kt * 64 + row) * D_ + seg * 8);
            cp16(base + vOff * 2 + so, vp + (size_t)(kt * 64 + row) * D_ + seg * 8);
        }
    };

    // EARLY: kick off kt=0 K/V into buf1 before Q staging (hides first DRAM hit).
    // Loop below reads tile kt from buffer (kt+1)&1, so kt=0 -> buf1.
    stage(1, 0);
    CP_COMMIT();

    // ---- stage 128 Q rows into buf0 + ones columns (both buffers) ----
#pragma unroll
    for (int i = 0; i < 8; i++) {
        int u = tid + 128 * i;
        int row = u >> 3, seg = u & 7;
        *reinterpret_cast<uint4*>(&smb[row * AT_S + seg * 8]) =
            *reinterpret_cast<const uint4*>(qp + (size_t)(qbase + row) * D_ + seg * 8);
    }
    for (int i = tid; i < 2 * 64 * 8; i += 128) {
        int s = i >> 9, r = (i >> 3) & 63, c = i & 7;
        smb[s * AT_BUF + vOff + r * AT_S + 64 + c] =
            (c == 0) ? __float2half(1.f) : __float2half(0.f);
    }
    __syncthreads();

    uint32_t aQA[4][4], aQB[4][4], eF[2];
    {
        const int aRow = lane & 15, aSeg = (lane >> 4) * 8;
#pragma unroll
        for (int ks = 0; ks < 4; ks++) {
            uint32_t offA = (uint32_t)((wid * 16 + aRow) * AT_S + ks * 16 + aSeg) * 2;
            ldsm_x4(aQA[ks], sbase + offA);
            uint32_t offB = (uint32_t)((64 + wid * 16 + aRow) * AT_S + ks * 16 + aSeg) * 2;
            ldsm_x4(aQB[ks], sbase + offB);
        }
        // ones column lives in BOTH buffers; use buf1's (not clobbered by Q)
        uint32_t eoff = (uint32_t)(AT_BUF + vOff +
            ((lane & 7) + ((lane >> 3) & 1) * 8) * AT_S + 64) * 2;
        ldsm_x2t(eF, sbase + eoff);
    }
    __syncthreads();

    float oaccA[8][4], oaccB[8][4], oaccEA[4], oaccEB[4];
#pragma unroll
    for (int nt = 0; nt < 8; nt++)
#pragma unroll
        for (int q = 0; q < 4; q++) { oaccA[nt][q] = 0.f; oaccB[nt][q] = 0.f; }
#pragma unroll
    for (int q = 0; q < 4; q++) { oaccEA[q] = 0.f; oaccEB[q] = 0.f; }

    const int bRowOff = (lane & 7) + ((lane >> 4) << 3);   // K: n-row
    const int bKoff = ((lane >> 3) & 1) * 8;               // K: k-col
    const int vRow = (lane & 7) + ((lane >> 3) & 1) * 8;   // V (trans): k-row
    const int vCol = ((lane >> 4) & 1) * 8;                // V: n-col
    const int ktmax = 2 * qt2 + 1;

    for (int kt = 0; kt <= ktmax; kt++) {
        CP_WAIT(0);
        __syncthreads();
        if (kt < ktmax) {
            stage(kt & 1, kt + 1);     // next tile -> buffer (kt+2)&1 == kt&1
            CP_COMMIT();
        }

        const uint32_t bK = sbase + (uint32_t)((kt + 1) & 1) * AT_BUF * 2;
        const uint32_t bV = bK + vOff * 2;

        // ---- process q-tiles sequentially (R14 structure, reg-frugal) ----
#pragma unroll
        for (int tb = 0; tb < 2; tb++) {
            const int klimit = 2 * qt2 + tb;
            if (kt > klimit) continue;
            float (*oacc)[4] = tb ? oaccB : oaccA;
            float* oaccE = tb ? oaccEB : oaccEA;
            uint32_t (*aQ)[4] = tb ? aQB : aQA;

            float sacc[8][4];
#pragma unroll
            for (int nt = 0; nt < 8; nt++)
#pragma unroll
                for (int q = 0; q < 4; q++) sacc[nt][q] = 0.f;
#pragma unroll
            for (int ks = 0; ks < 4; ks++) {
#pragma unroll
                for (int ng = 0; ng < 4; ng++) {
                    uint32_t boff = (uint32_t)((ng * 16 + bRowOff) * AT_S + ks * 16 + bKoff) * 2;
                    uint32_t bh4[4];
                    ldsm_x4(bh4, bK + boff);
                    mma16816h(sacc[ng * 2 + 0], aQ[ks], bh4[0], bh4[1]);
                    mma16816h(sacc[ng * 2 + 1], aQ[ks], bh4[2], bh4[3]);
                }
            }

            if (kt == klimit) {                  // diagonal: causal mask
#pragma unroll
                for (int nt = 0; nt < 8; nt++)
#pragma unroll
                    for (int j = 0; j < 4; j++) {
                        int rloc = wid * 16 + (lane >> 2) + (j >> 1) * 8;
                        int cloc = nt * 8 + (lane & 3) * 2 + (j & 1);
                        if (cloc > rloc) sacc[nt][j] = -1e30f;
                    }
            }

            uint32_t aP[4][4];
#pragma unroll
            for (int ks = 0; ks < 4; ks++) {
                aP[ks][0] = h2ex2(packh(sacc[2 * ks][0],     sacc[2 * ks][1]));
                aP[ks][1] = h2ex2(packh(sacc[2 * ks][2],     sacc[2 * ks][3]));
                aP[ks][2] = h2ex2(packh(sacc[2 * ks + 1][0], sacc[2 * ks + 1][1]));
                aP[ks][3] = h2ex2(packh(sacc[2 * ks + 1][2], sacc[2 * ks + 1][3]));
            }

#pragma unroll
            for (int ks = 0; ks < 4; ks++) {
#pragma unroll
                for (int ng = 0; ng < 4; ng++) {
                    uint32_t boff = (uint32_t)((ks * 16 + vRow) * AT_S + ng * 16 + vCol) * 2;
                    uint32_t vh4[4];
                    ldsm_x4t(vh4, bV + boff);
                    mma16816h(oacc[ng * 2 + 0], aP[ks], vh4[0], vh4[1]);
                    mma16816h(oacc[ng * 2 + 1], aP[ks], vh4[2], vh4[3]);
                }
                mma16816h(oaccE, aP[ks], eF[0], eF[1]);
            }
        }
    }

    // normalize: row sum in ones-tile col 0 (lanes with lane%4==0)
#pragma unroll
    for (int tb = 0; tb < 2; tb++) {
        float (*oacc)[4] = tb ? oaccB : oaccA;
        float* oaccE = tb ? oaccEB : oaccEA;
#pragma unroll
        for (int hf = 0; hf < 2; hf++) {
            float l = __shfl_sync(0xffffffffu, oaccE[hf * 2], lane & 28);
            int q = qbase + tb * 64 + wid * 16 + (lane >> 2) + hf * 8;
            float inv = 1.0f / l;
            size_t basei = (size_t)(b * T_ + q) * E_ + h * 64 + (lane & 3) * 2;
#pragma unroll
            for (int nt = 0; nt < 8; nt++) {
                *reinterpret_cast<uint32_t*>(g_ah + basei + nt * 8) =
                    packh(oacc[nt][hf * 2 + 0] * inv, oacc[nt][hf * 2 + 1] * inv);
            }
        }
    }
}

// ================= launcher =================
extern "C" void kernel_launch(void* const* d_in, const int* in_sizes, int n_in,
                              void* d_out, int out_size) {
    const float* x  = (const float*)d_in[0];
    const float* Wq = (const float*)d_in[1];
    const float* Wk = (const float*)d_in[2];
    const float* Wv = (const float*)d_in[3];
    const float* Wo = (const float*)d_in[4];
    const float* bo = (const float*)d_in[5];
    float* out = (float*)d_out;

    cudaFuncSetAttribute(gemm_kernel<0>, cudaFuncAttributeMaxDynamicSharedMemorySize, GM_SMEM_BYTES);
    cudaFuncSetAttribute(gemm_kernel<1>, cudaFuncAttributeMaxDynamicSharedMemorySize, GM_SMEM_BYTES);

    conv_kernel<<<CONVX_BLOCKS + CONVW_BLOCKS, 256>>>(x, Wq, Wk, Wv, Wo);

    dim3 g1(NQKV_ / 128, BT_ / 128);
    gemm_kernel<0><<<g1, 256, GM_SMEM_BYTES>>>(nullptr, nullptr);

    dim3 g2(T_ / 128, H_, B_);
    attn_kernel<<<g2, 128>>>();

    dim3 g3(E_ / 128, BT_ / 128);
    gemm_kernel<1><<<g3, 256, GM_SMEM_BYTES>>>(out, bo);
}